// round 14
// baseline (speedup 1.0000x reference)
#include <cuda_runtime.h>

#define BATCH 4
#define CH    64
#define HH    128
#define WW    128
#define HW    (HH*WW)
#define J18   18
#define CK    576   /* CH*9 */

// Device-global scratch
__device__ float g_xt[BATCH*HW*CH];    // x NHWC [b][h][w][c]   16 MB
__device__ float g_off[BATCH*HW*J18];  // offsets [b][h][w][j]  4.5 MB
__device__ float g_wT[CK*CH];          // W [k=tap*64+c][o]     147 KB

__device__ __forceinline__ void fma2(unsigned long long& a,
                                     unsigned long long b,
                                     unsigned long long c) {
    asm("fma.rn.f32x2 %0, %1, %2, %0;" : "+l"(a) : "l"(b), "l"(c));
}
__device__ __forceinline__ unsigned long long dup2(float v) {
    unsigned long long r;
    asm("mov.b64 %0, {%1,%1};" : "=l"(r) : "f"(v));
    return r;
}
__device__ __forceinline__ unsigned long long pack2(float a, float b) {
    unsigned long long r;
    asm("mov.b64 %0, {%1,%2};" : "=l"(r) : "f"(a), "f"(b));
    return r;
}
__device__ __forceinline__ void unpack2(unsigned long long v, float& a, float& b) {
    asm("mov.b64 {%0,%1}, %2;" : "=f"(a), "=f"(b) : "l"(v));
}

// ---------------------------------------------------------------------------
// Repack main weight: [o][c][tap] -> [k=tap*64+c][o]
// ---------------------------------------------------------------------------
__global__ void k_prep_wT(const float* __restrict__ weight) {
    int i = blockIdx.x * 256 + threadIdx.x;
    if (i >= CK * CH) return;
    int o = i & 63, k = i >> 6;
    int tap = k >> 6, c = k & 63;
    g_wT[k * 64 + o] = weight[(o * CH + c) * 9 + tap];
}

// ---------------------------------------------------------------------------
// NCHW -> NHWC transpose of x
// ---------------------------------------------------------------------------
__global__ void k_transpose(const float* __restrict__ x) {
    __shared__ float t[32][33];
    int b  = blockIdx.z;
    int c0 = blockIdx.y * 32;
    int p0 = blockIdx.x * 32;
    int tx = threadIdx.x, ty = threadIdx.y;   // 32 x 8
    const float* xb = x + (size_t)b * CH * HW;
#pragma unroll
    for (int i = 0; i < 4; i++)
        t[ty + i * 8][tx] = xb[(c0 + ty + i * 8) * HW + p0 + tx];
    __syncthreads();
    float* dst = g_xt + (size_t)b * HW * CH;
#pragma unroll
    for (int i = 0; i < 4; i++)
        dst[(p0 + ty + i * 8) * CH + c0 + tx] = t[tx][ty + i * 8];
}

// ---------------------------------------------------------------------------
// Offset conv: Conv2d(64 -> 18, 3x3, pad 1) on NCHW x, f32x2 accumulation.
// ---------------------------------------------------------------------------
__global__ void k_offconv(const float* __restrict__ x,
                          const float* __restrict__ w_off,
                          const float* __restrict__ b_off) {
    __shared__ __align__(16) float ws[CH * 9 * 20];
    int tid = threadIdx.y * 32 + threadIdx.x;
    for (int i = tid; i < CH * 9 * J18; i += 128) {
        int j = i % 18; int t = i / 18; int tap = t % 9; int c = t / 9;
        ws[(c * 9 + tap) * 20 + j] = w_off[(j * CH + c) * 9 + tap];
    }
    __syncthreads();

    int b = blockIdx.z;
    int h = blockIdx.y * 4 + threadIdx.y;
    int w = blockIdx.x * 32 + threadIdx.x;

    unsigned long long acc2[9];
#pragma unroll
    for (int q = 0; q < 9; q++)
        acc2[q] = pack2(__ldg(b_off + 2 * q), __ldg(b_off + 2 * q + 1));

    const float* xb = x + (size_t)b * CH * HW;
    for (int c = 0; c < CH; c++) {
        const float* xc = xb + c * HW;
#pragma unroll
        for (int r = 0; r < 3; r++) {
            int y = h + r - 1;
            if ((unsigned)y < (unsigned)HH) {
                const float* xr = xc + y * WW;
                float v0 = (w >= 1)      ? __ldg(xr + w - 1) : 0.f;
                float v1 =                 __ldg(xr + w);
                float v2 = (w < WW - 1)  ? __ldg(xr + w + 1) : 0.f;
                const float* wsr = ws + (c * 9 + r * 3) * 20;
#pragma unroll
                for (int s = 0; s < 3; s++) {
                    float val = (s == 0) ? v0 : ((s == 1) ? v1 : v2);
                    unsigned long long vd = dup2(val);
                    const double2* wp = (const double2*)(wsr + s * 20);
                    double2 p0 = wp[0], p1 = wp[1];
                    double2 p2 = wp[2], p3 = wp[3];
                    double   p4 = *(const double*)(wsr + s * 20 + 16);
                    fma2(acc2[0], vd, __double_as_longlong(p0.x));
                    fma2(acc2[1], vd, __double_as_longlong(p0.y));
                    fma2(acc2[2], vd, __double_as_longlong(p1.x));
                    fma2(acc2[3], vd, __double_as_longlong(p1.y));
                    fma2(acc2[4], vd, __double_as_longlong(p2.x));
                    fma2(acc2[5], vd, __double_as_longlong(p2.y));
                    fma2(acc2[6], vd, __double_as_longlong(p3.x));
                    fma2(acc2[7], vd, __double_as_longlong(p3.y));
                    fma2(acc2[8], vd, __double_as_longlong(p4));
                }
            }
        }
    }

    __syncthreads();
#pragma unroll
    for (int q = 0; q < 9; q++) {
        float a, bb;
        unpack2(acc2[q], a, bb);
        ws[threadIdx.y * 576 + threadIdx.x * 18 + 2 * q]     = a;
        ws[threadIdx.y * 576 + threadIdx.x * 18 + 2 * q + 1] = bb;
    }
    __syncthreads();
    for (int i = tid; i < 4 * 576; i += 128) {
        int row = i / 576, col = i % 576;
        int h2 = blockIdx.y * 4 + row;
        g_off[((size_t)b * HW + h2 * WW + blockIdx.x * 32) * 18 + col] = ws[row * 576 + col];
    }
}

// ---------------------------------------------------------------------------
// Fused deform+GEMM. CTA = 64 o x 128 px (one FULL image row) -> W traffic
// per pixel halved vs 64-px tiles. 256 threads, thread tile 4o x 8px,
// f32x2 paired over (px,px+1). S non-duplicated padded rows (132 floats =
// 528B: conflict-free STS/LDS, no swizzle). Coords double-buffered per tap:
// tap t+1's idx4/wt4 computed during tap t's gather phase (threads <128).
// smem: S 33KB + coords 8KB = 41KB -> 4 CTAs/SM.
// ---------------------------------------------------------------------------
#define SROW 132                /* S row stride in floats (528B) */
#define SMEM_MAIN (64*SROW*4 + 2*128*16 + 2*128*16)   /* 33792+4096+4096 */

__global__ void __launch_bounds__(256, 4) k_main(float* __restrict__ out) {
    extern __shared__ __align__(16) float sm[];
    float*  sS   = sm;                              // [64 c][132] padded
    int4*   cIdx = (int4*)(sm + 64 * SROW);         // [2][128]
    float4* cWt  = (float4*)(sm + 64 * SROW + 1024);// [2][128]

    int b = blockIdx.y;
    int h = blockIdx.x;
    int tid  = threadIdx.x;
    int warp = tid >> 5, lane = tid & 31;

    const float* xt = g_xt + (size_t)b * HW * CH;
    const float* offrow = g_off + ((size_t)b * HW + h * WW) * 18;

    // ---- coord computation for one tap into slot s (threads < 128) ----
    auto compute_coords = [&](int tap, int slot) {
        if (tid < 128) {
            int w = tid;
            const float* op = offrow + w * 18 + tap * 2;
            float dy = __ldg(op), dx = __ldg(op + 1);
            float py  = (float)(h + tap / 3 - 1) + dy;
            float pxf = (float)(w + tap % 3 - 1) + dx;
            float fy = floorf(py), fx = floorf(pxf);
            int y0 = (int)fy, x0 = (int)fx;
            float ly = py - fy, lx = pxf - fx;
            float hy = 1.f - ly, hx = 1.f - lx;
            float my0 = ((unsigned)y0       < (unsigned)HH) ? 1.f : 0.f;
            float my1 = ((unsigned)(y0 + 1) < (unsigned)HH) ? 1.f : 0.f;
            float mx0 = ((unsigned)x0       < (unsigned)WW) ? 1.f : 0.f;
            float mx1 = ((unsigned)(x0 + 1) < (unsigned)WW) ? 1.f : 0.f;
            int y0c = min(max(y0, 0), HH - 1);
            int y1c = min(max(y0 + 1, 0), HH - 1);
            int x0c = min(max(x0, 0), WW - 1);
            int x1c = min(max(x0 + 1, 0), WW - 1);
            cIdx[slot * 128 + w] = make_int4(
                (y0c * WW + x0c) * CH, (y0c * WW + x1c) * CH,
                (y1c * WW + x0c) * CH, (y1c * WW + x1c) * CH);
            cWt[slot * 128 + w] = make_float4(
                hy * hx * my0 * mx0, hy * lx * my0 * mx1,
                ly * hx * my1 * mx0, ly * lx * my1 * mx1);
        }
    };

    compute_coords(0, 0);
    __syncthreads();

    int o_grp = tid & 15, px_grp = tid >> 4;    // 16 o-groups x 16 px-groups
    int o_base = o_grp * 4;
    unsigned long long acc[4][4];
#pragma unroll
    for (int o = 0; o < 4; o++)
#pragma unroll
        for (int p = 0; p < 4; p++) acc[o][p] = 0ULL;

    unsigned sSsh = (unsigned)__cvta_generic_to_shared(sS) + px_grp * 32;

    for (int tap = 0; tap < 9; tap++) {
        int slot = tap & 1;
        // ---- Phase A: gather 64 tasks (2 chalf x 32 pxg) over 8 warps ----
        for (int task = warp; task < 64; task += 8) {
            int chalf = task & 1, pxg = task >> 1;
            int c = chalf * 32 + lane;
            const float* xc = xt + c;
            float rv[4];
#pragma unroll
            for (int i = 0; i < 4; i++) {
                int e = slot * 128 + pxg * 4 + i;
                int4   ix = cIdx[e];
                float4 wt = cWt[e];
                rv[i] = wt.x * __ldg(xc + ix.x) + wt.y * __ldg(xc + ix.y)
                      + wt.z * __ldg(xc + ix.z) + wt.w * __ldg(xc + ix.w);
            }
            *(float4*)(sS + c * SROW + pxg * 4) =
                make_float4(rv[0], rv[1], rv[2], rv[3]);
        }
        if (tap < 8) compute_coords(tap + 1, slot ^ 1);
        __syncthreads();

        // ---- Phase B: GEMM partial over 64 k ----
        const float* wtap = g_wT + (size_t)(tap * 64) * 64 + o_base;
#pragma unroll 8
        for (int k = 0; k < 64; k++) {
            float4 wv = __ldg((const float4*)(wtap + k * 64));
            unsigned long long s01, s23, s45, s67;
            asm("ld.shared.v2.b64 {%0,%1},[%2];"
                : "=l"(s01), "=l"(s23) : "r"(sSsh + k * (SROW * 4)));
            asm("ld.shared.v2.b64 {%0,%1},[%2];"
                : "=l"(s45), "=l"(s67) : "r"(sSsh + k * (SROW * 4) + 16));
            unsigned long long w0d = dup2(wv.x), w1d = dup2(wv.y);
            unsigned long long w2d = dup2(wv.z), w3d = dup2(wv.w);
            fma2(acc[0][0], w0d, s01); fma2(acc[0][1], w0d, s23);
            fma2(acc[0][2], w0d, s45); fma2(acc[0][3], w0d, s67);
            fma2(acc[1][0], w1d, s01); fma2(acc[1][1], w1d, s23);
            fma2(acc[1][2], w1d, s45); fma2(acc[1][3], w1d, s67);
            fma2(acc[2][0], w2d, s01); fma2(acc[2][1], w2d, s23);
            fma2(acc[2][2], w2d, s45); fma2(acc[2][3], w2d, s67);
            fma2(acc[3][0], w3d, s01); fma2(acc[3][1], w3d, s23);
            fma2(acc[3][2], w3d, s45); fma2(acc[3][3], w3d, s67);
        }
        __syncthreads();
    }

    // ---- Epilogue: 4 output rows (o), 8 contiguous px each ----
    int w = px_grp * 8;
    float* ob = out + (((size_t)b * CH + o_base) * HH + h) * WW + w;
#pragma unroll
    for (int o = 0; o < 4; o++) {
        float r0, r1, r2, r3, r4, r5, r6, r7;
        unpack2(acc[o][0], r0, r1);
        unpack2(acc[o][1], r2, r3);
        unpack2(acc[o][2], r4, r5);
        unpack2(acc[o][3], r6, r7);
        *(float4*)(ob + (size_t)o * HW)     = make_float4(r0, r1, r2, r3);
        *(float4*)(ob + (size_t)o * HW + 4) = make_float4(r4, r5, r6, r7);
    }
}

// ---------------------------------------------------------------------------
extern "C" void kernel_launch(void* const* d_in, const int* in_sizes, int n_in,
                              void* d_out, int out_size) {
    const float* x      = (const float*)d_in[0];
    const float* w_off  = (const float*)d_in[1];
    const float* b_off  = (const float*)d_in[2];
    const float* weight = (const float*)d_in[3];
    float* out = (float*)d_out;

    cudaFuncSetAttribute(k_main, cudaFuncAttributeMaxDynamicSharedMemorySize,
                         SMEM_MAIN);

    k_prep_wT<<<(CK * CH + 255) / 256, 256>>>(weight);
    k_transpose<<<dim3(HW / 32, CH / 32, BATCH), dim3(32, 8)>>>(x);
    k_offconv<<<dim3(WW / 32, HH / 4, BATCH), dim3(32, 4)>>>(x, w_off, b_off);
    k_main<<<dim3(HH, BATCH), 256, SMEM_MAIN>>>(out);
}

// round 15
// speedup vs baseline: 1.6700x; 1.6700x over previous
#include <cuda_runtime.h>

#define BATCH 4
#define CH    64
#define HH    128
#define WW    128
#define HW    (HH*WW)
#define J18   18
#define CK    576   /* CH*9 */

// Device-global scratch
__device__ float g_xt[BATCH*HW*CH];    // x NHWC [b][h][w][c]   16 MB
__device__ float g_off[BATCH*HW*J18];  // offsets [b][h][w][j]  4.5 MB
__device__ float g_wT[CK*CH];          // W [k=tap*64+c][o]     147 KB

__device__ __forceinline__ void fma2(unsigned long long& a,
                                     unsigned long long b,
                                     unsigned long long c) {
    asm("fma.rn.f32x2 %0, %1, %2, %0;" : "+l"(a) : "l"(b), "l"(c));
}
__device__ __forceinline__ unsigned long long dup2(float v) {
    unsigned long long r;
    asm("mov.b64 %0, {%1,%1};" : "=l"(r) : "f"(v));
    return r;
}
__device__ __forceinline__ unsigned long long pack2(float a, float b) {
    unsigned long long r;
    asm("mov.b64 %0, {%1,%2};" : "=l"(r) : "f"(a), "f"(b));
    return r;
}
__device__ __forceinline__ void unpack2(unsigned long long v, float& a, float& b) {
    asm("mov.b64 {%0,%1}, %2;" : "=f"(a), "=f"(b) : "l"(v));
}

// ---------------------------------------------------------------------------
// Repack main weight: [o][c][tap] -> [k=tap*64+c][o]
// ---------------------------------------------------------------------------
__global__ void k_prep_wT(const float* __restrict__ weight) {
    int i = blockIdx.x * 256 + threadIdx.x;
    if (i >= CK * CH) return;
    int o = i & 63, k = i >> 6;
    int tap = k >> 6, c = k & 63;
    g_wT[k * 64 + o] = weight[(o * CH + c) * 9 + tap];
}

// ---------------------------------------------------------------------------
// NCHW -> NHWC transpose of x
// ---------------------------------------------------------------------------
__global__ void k_transpose(const float* __restrict__ x) {
    __shared__ float t[32][33];
    int b  = blockIdx.z;
    int c0 = blockIdx.y * 32;
    int p0 = blockIdx.x * 32;
    int tx = threadIdx.x, ty = threadIdx.y;   // 32 x 8
    const float* xb = x + (size_t)b * CH * HW;
#pragma unroll
    for (int i = 0; i < 4; i++)
        t[ty + i * 8][tx] = xb[(c0 + ty + i * 8) * HW + p0 + tx];
    __syncthreads();
    float* dst = g_xt + (size_t)b * HW * CH;
#pragma unroll
    for (int i = 0; i < 4; i++)
        dst[(p0 + ty + i * 8) * CH + c0 + tx] = t[tx][ty + i * 8];
}

// ---------------------------------------------------------------------------
// Offset conv: Conv2d(64 -> 18, 3x3, pad 1) on NCHW x, f32x2 accumulation.
// ---------------------------------------------------------------------------
__global__ void k_offconv(const float* __restrict__ x,
                          const float* __restrict__ w_off,
                          const float* __restrict__ b_off) {
    __shared__ __align__(16) float ws[CH * 9 * 20];
    int tid = threadIdx.y * 32 + threadIdx.x;
    for (int i = tid; i < CH * 9 * J18; i += 128) {
        int j = i % 18; int t = i / 18; int tap = t % 9; int c = t / 9;
        ws[(c * 9 + tap) * 20 + j] = w_off[(j * CH + c) * 9 + tap];
    }
    __syncthreads();

    int b = blockIdx.z;
    int h = blockIdx.y * 4 + threadIdx.y;
    int w = blockIdx.x * 32 + threadIdx.x;

    unsigned long long acc2[9];
#pragma unroll
    for (int q = 0; q < 9; q++)
        acc2[q] = pack2(__ldg(b_off + 2 * q), __ldg(b_off + 2 * q + 1));

    const float* xb = x + (size_t)b * CH * HW;
    for (int c = 0; c < CH; c++) {
        const float* xc = xb + c * HW;
#pragma unroll
        for (int r = 0; r < 3; r++) {
            int y = h + r - 1;
            if ((unsigned)y < (unsigned)HH) {
                const float* xr = xc + y * WW;
                float v0 = (w >= 1)      ? __ldg(xr + w - 1) : 0.f;
                float v1 =                 __ldg(xr + w);
                float v2 = (w < WW - 1)  ? __ldg(xr + w + 1) : 0.f;
                const float* wsr = ws + (c * 9 + r * 3) * 20;
#pragma unroll
                for (int s = 0; s < 3; s++) {
                    float val = (s == 0) ? v0 : ((s == 1) ? v1 : v2);
                    unsigned long long vd = dup2(val);
                    const double2* wp = (const double2*)(wsr + s * 20);
                    double2 p0 = wp[0], p1 = wp[1];
                    double2 p2 = wp[2], p3 = wp[3];
                    double   p4 = *(const double*)(wsr + s * 20 + 16);
                    fma2(acc2[0], vd, __double_as_longlong(p0.x));
                    fma2(acc2[1], vd, __double_as_longlong(p0.y));
                    fma2(acc2[2], vd, __double_as_longlong(p1.x));
                    fma2(acc2[3], vd, __double_as_longlong(p1.y));
                    fma2(acc2[4], vd, __double_as_longlong(p2.x));
                    fma2(acc2[5], vd, __double_as_longlong(p2.y));
                    fma2(acc2[6], vd, __double_as_longlong(p3.x));
                    fma2(acc2[7], vd, __double_as_longlong(p3.y));
                    fma2(acc2[8], vd, __double_as_longlong(p4));
                }
            }
        }
    }

    __syncthreads();
#pragma unroll
    for (int q = 0; q < 9; q++) {
        float a, bb;
        unpack2(acc2[q], a, bb);
        ws[threadIdx.y * 576 + threadIdx.x * 18 + 2 * q]     = a;
        ws[threadIdx.y * 576 + threadIdx.x * 18 + 2 * q + 1] = bb;
    }
    __syncthreads();
    for (int i = tid; i < 4 * 576; i += 128) {
        int row = i / 576, col = i % 576;
        int h2 = blockIdx.y * 4 + row;
        g_off[((size_t)b * HW + h2 * WW + blockIdx.x * 32) * 18 + col] = ws[row * 576 + col];
    }
}

// ---------------------------------------------------------------------------
// Fused deform+GEMM. CTA = 64 o x 64 px strip, 256 threads, tile 4o x 4px,
// f32x2 paired over (px,px+1). S DOUBLE-BUFFERED non-dup padded rows (68
// floats = 272B, conflict-free STS/LDS, no swizzle). Per tap, ONE sync:
// gather(t+1) -> buf B overlaps GEMM(t) <- buf A (no barrier between them;
// warps cover each other's stalls). W prefetched one k ahead so the dup
// movs never wait on an in-flight LDG. smem 53.2KB -> 4 CTAs/SM.
// ---------------------------------------------------------------------------
#define NPT  576                /* 9 taps x 64 px */
#define SROW 68                 /* S row stride in floats (272B) */
#define SBUF (64*SROW)          /* floats per S buffer */
#define SMEM_MAIN (2*SBUF*4 + NPT*16 + NPT*16)   /* 34816+9216+9216=53248 */

__global__ void __launch_bounds__(256, 4) k_main(float* __restrict__ out) {
    extern __shared__ __align__(16) float sm[];
    float*  sS   = sm;                              // [2][64][68]
    int4*   sIdx = (int4*)(sm + 2 * SBUF);          // [576]
    float4* sWt  = (float4*)(sm + 2 * SBUF + NPT * 4);

    int b  = blockIdx.z;
    int h  = blockIdx.y;
    int w0 = blockIdx.x * 64;
    int tid  = threadIdx.x;
    int warp = tid >> 5, lane = tid & 31;

    const float* xt = g_xt + (size_t)b * HW * CH;

    // ---- Precompute bilinear coords: entry e = tap*64 + px ----
    for (int e = tid; e < NPT; e += 256) {
        int tap = e >> 6, px = e & 63;
        int w = w0 + px;
        const float* op = g_off + ((size_t)b * HW + h * WW + w) * 18 + tap * 2;
        float dy = __ldg(op), dx = __ldg(op + 1);
        float py  = (float)(h + tap / 3 - 1) + dy;
        float pxf = (float)(w + tap % 3 - 1) + dx;
        float fy = floorf(py), fx = floorf(pxf);
        int y0 = (int)fy, x0 = (int)fx;
        float ly = py - fy, lx = pxf - fx;
        float hy = 1.f - ly, hx = 1.f - lx;
        float my0 = ((unsigned)y0       < (unsigned)HH) ? 1.f : 0.f;
        float my1 = ((unsigned)(y0 + 1) < (unsigned)HH) ? 1.f : 0.f;
        float mx0 = ((unsigned)x0       < (unsigned)WW) ? 1.f : 0.f;
        float mx1 = ((unsigned)(x0 + 1) < (unsigned)WW) ? 1.f : 0.f;
        int y0c = min(max(y0, 0), HH - 1);
        int y1c = min(max(y0 + 1, 0), HH - 1);
        int x0c = min(max(x0, 0), WW - 1);
        int x1c = min(max(x0 + 1, 0), WW - 1);
        sIdx[e] = make_int4((y0c * WW + x0c) * CH, (y0c * WW + x1c) * CH,
                            (y1c * WW + x0c) * CH, (y1c * WW + x1c) * CH);
        sWt[e]  = make_float4(hy * hx * my0 * mx0, hy * lx * my0 * mx1,
                              ly * hx * my1 * mx0, ly * lx * my1 * mx1);
    }
    __syncthreads();

    int o_grp = tid & 15, px_grp = tid >> 4;    // 16 o-groups x 16 px-groups
    int o_base = o_grp * 4;
    unsigned long long acc[4][2];
#pragma unroll
    for (int p = 0; p < 4; p++) { acc[p][0] = 0ULL; acc[p][1] = 0ULL; }

    unsigned sSsh = (unsigned)__cvta_generic_to_shared(sS) + px_grp * 16;

    // ---- gather one tap into S buffer bsel ----
    auto gather = [&](int tap, int bsel) {
        float* sbuf = sS + bsel * SBUF;
        for (int task = warp; task < 32; task += 8) {
            int chalf = task & 1, pxg = task >> 1;
            int c = chalf * 32 + lane;
            const float* xc = xt + c;
            float rv[4];
#pragma unroll
            for (int i = 0; i < 4; i++) {
                int e = tap * 64 + pxg * 4 + i;
                int4   ix = sIdx[e];
                float4 wt = sWt[e];
                rv[i] = wt.x * __ldg(xc + ix.x) + wt.y * __ldg(xc + ix.y)
                      + wt.z * __ldg(xc + ix.z) + wt.w * __ldg(xc + ix.w);
            }
            *(float4*)(sbuf + c * SROW + pxg * 4) =
                make_float4(rv[0], rv[1], rv[2], rv[3]);
        }
    };

    gather(0, 0);
    __syncthreads();

    for (int tap = 0; tap < 9; tap++) {
        int bsel = tap & 1;
        // ---- issue next tap's gather (writes other buffer, no barrier) ----
        if (tap < 8) gather(tap + 1, bsel ^ 1);

        // ---- GEMM partial over 64 k from current buffer ----
        const float* wtap = g_wT + (size_t)(tap * 64) * 64 + o_base;
        unsigned sb = sSsh + bsel * (SBUF * 4);
        float4 wv = __ldg((const float4*)wtap);
#pragma unroll 8
        for (int k = 0; k < 64; k++) {
            float4 wn;
            if (k < 63) wn = __ldg((const float4*)(wtap + (k + 1) * 64));
            unsigned long long s01, s23;
            asm("ld.shared.v2.b64 {%0,%1},[%2];"
                : "=l"(s01), "=l"(s23) : "r"(sb + k * (SROW * 4)));
            unsigned long long w0d = dup2(wv.x), w1d = dup2(wv.y);
            unsigned long long w2d = dup2(wv.z), w3d = dup2(wv.w);
            fma2(acc[0][0], w0d, s01); fma2(acc[0][1], w0d, s23);
            fma2(acc[1][0], w1d, s01); fma2(acc[1][1], w1d, s23);
            fma2(acc[2][0], w2d, s01); fma2(acc[2][1], w2d, s23);
            fma2(acc[3][0], w3d, s01); fma2(acc[3][1], w3d, s23);
            wv = wn;
        }
        __syncthreads();
    }

    // ---- Epilogue: 4 output rows (o), 4 contiguous px each ----
    int w = w0 + px_grp * 4;
    float* ob = out + (((size_t)b * CH + o_base) * HH + h) * WW + w;
#pragma unroll
    for (int p = 0; p < 4; p++) {
        float r0, r1, r2, r3;
        unpack2(acc[p][0], r0, r1);
        unpack2(acc[p][1], r2, r3);
        *(float4*)(ob + (size_t)p * HW) = make_float4(r0, r1, r2, r3);
    }
}

// ---------------------------------------------------------------------------
extern "C" void kernel_launch(void* const* d_in, const int* in_sizes, int n_in,
                              void* d_out, int out_size) {
    const float* x      = (const float*)d_in[0];
    const float* w_off  = (const float*)d_in[1];
    const float* b_off  = (const float*)d_in[2];
    const float* weight = (const float*)d_in[3];
    float* out = (float*)d_out;

    cudaFuncSetAttribute(k_main, cudaFuncAttributeMaxDynamicSharedMemorySize,
                         SMEM_MAIN);

    k_prep_wT<<<(CK * CH + 255) / 256, 256>>>(weight);
    k_transpose<<<dim3(HW / 32, CH / 32, BATCH), dim3(32, 8)>>>(x);
    k_offconv<<<dim3(WW / 32, HH / 4, BATCH), dim3(32, 4)>>>(x, w_off, b_off);
    k_main<<<dim3(WW / 64, HH, BATCH), 256, SMEM_MAIN>>>(out);
}